// round 15
// baseline (speedup 1.0000x reference)
#include <cuda_runtime.h>
#include <cuda_fp16.h>

// CRF NLL, B=256, S=256, T=128 (126 tags + START/STOP)
// Split-chain forward/backward:  Z_b = sum_i alpha_m[i] * beta_m[i]
//   alpha_t[j] = (sum_i alpha_{t-1}[i] E[i,j]) * exp(f_t[j])     (fwd, m rounds)
//   beta_{t-1}[i] = sum_j E[i,j] exp(f_t[j]) beta_t[j]           (bwd, len-1-m)
// 512 tasks (2 per chain, depth ~(len-1)/2) scheduled over 296 CTA-halves:
// 80 largest solo (40 CTAs), rest paired large-with-small (sums ~const 181).
// Inner loop = R12's validated fp16 HFMA2 matvec (E rows/cols in 64 half2
// regs, per-step normalization by M=max(w0,w1,w64,w65), fp32 N bookkeeping).
// Last CTA (ticket) combines: log(dot(alpha_m,beta_m)) + Nf + Nb - gold.

#define B_    256
#define S_    256
#define T_    128
#define NCTA  148
#define NHALF (2 * NCTA)          // 296
#define NSOLOH (2 * NHALF - 2 * B_)  // 80 halves carrying a single task
#define LOG128 4.852030263919617f

__device__ float g_alpha[B_][T_];
__device__ float g_beta[B_][T_];
__device__ float g_Nf[B_];
__device__ float g_Nb[B_];
__device__ float g_gold[B_];
__device__ unsigned g_task[2 * NHALF];  // per half: 2 slots; 0 = empty
__device__ unsigned g_ticket;           // zero-init; reset by last CTA

#define BARH(id) \
    asm volatile("bar.sync %0, 128;" :: "r"(id) : "memory")

__device__ __forceinline__ float rcpa(float x) {
    float r; asm("rcp.approx.f32 %0, %1;" : "=f"(r) : "f"(x)); return r;
}
__device__ __forceinline__ __half2 u2h(unsigned u) {
    __half2 h;
    *reinterpret_cast<unsigned*>(&h) = u;
    return h;
}
__device__ __forceinline__ float warpSum(float x) {
#pragma unroll
    for (int o = 16; o; o >>= 1) x += __shfl_xor_sync(0xffffffffu, x, o);
    return x;
}

// ---- prep: lengths, 512 task keys, bitonic sort desc, assign to halves ----
// key = (rounds<<23) | (len<<14) | (b<<1) | dir   (dir 0=fwd, 1=bwd)
__global__ void prep_kernel(const int* __restrict__ mask) {
    __shared__ unsigned key[2 * B_];
    const int t = threadIdx.x;
    if (t < B_) {
        const int* mb = mask + t * S_;
        int lo = S_ / 2, hi = S_;           // len in [S/2, S], prefix mask
        while (lo < hi) {                   // 7 iterations
            int mid = (lo + hi) >> 1;
            if (mb[mid]) lo = mid + 1; else hi = mid;
        }
        unsigned len = (unsigned)lo;
        unsigned rf = (len - 1) >> 1;       // fwd rounds = m
        unsigned rb = (len - 1) - rf;       // bwd rounds
        key[2 * t]     = (rf << 23) | (len << 14) | ((unsigned)t << 1) | 0u;
        key[2 * t + 1] = (rb << 23) | (len << 14) | ((unsigned)t << 1) | 1u;
    }
    __syncthreads();
    for (int k = 2; k <= 2 * B_; k <<= 1) {
        for (int jj = k >> 1; jj; jj >>= 1) {
            int ixj = t ^ jj;
            if (ixj > t) {
                unsigned a = key[t], c = key[ixj];
                bool up = (t & k) == 0;     // descending
                if (up ? (a < c) : (a > c)) { key[t] = c; key[ixj] = a; }
            }
            __syncthreads();
        }
    }
    if (t < NHALF) {
        unsigned s0, s1;
        if (t < NSOLOH) { s0 = key[t]; s1 = 0u; }
        else {
            int k = t - NSOLOH;
            s0 = key[NSOLOH + k];
            s1 = key[2 * B_ - 1 - k];
        }
        g_task[2 * t]     = s0;
        g_task[2 * t + 1] = s1;
    }
}

// fp16 matvec over shared vector wsrc with per-step normalization.
__device__ __forceinline__ float hmatvec(const __half* __restrict__ wsrc,
                                         const __half2* __restrict__ eh,
                                         float& N, float& scale)
{
    const uint4* vv = reinterpret_cast<const uint4*>(wsrc);
    uint4 x0 = vv[0], x1 = vv[1], x2 = vv[2], x3 = vv[3];
    unsigned uw64 = *reinterpret_cast<const unsigned*>(wsrc + 64);

    __half2 mm = __hmax2(u2h(x0.x), u2h(uw64));
    float M = fmaxf(__low2float(mm), __high2float(mm));
    scale = rcpa(M) * 0.0078125f;           // 1/(128*M)
    N += __logf(M) + LOG128;

    __half2 a0 = __hmul2(u2h(x0.x), eh[0]);
    __half2 a1 = __hmul2(u2h(x0.y), eh[1]);
    __half2 a2 = __hmul2(u2h(x0.z), eh[2]);
    __half2 a3 = __hmul2(u2h(x0.w), eh[3]);
    __half2 a4 = __hmul2(u2h(x1.x), eh[4]);
    __half2 a5 = __hmul2(u2h(x1.y), eh[5]);
    __half2 a6 = __hmul2(u2h(x1.z), eh[6]);
    __half2 a7 = __hmul2(u2h(x1.w), eh[7]);
    a0 = __hfma2(u2h(x2.x), eh[8],  a0);
    a1 = __hfma2(u2h(x2.y), eh[9],  a1);
    a2 = __hfma2(u2h(x2.z), eh[10], a2);
    a3 = __hfma2(u2h(x2.w), eh[11], a3);
    a4 = __hfma2(u2h(x3.x), eh[12], a4);
    a5 = __hfma2(u2h(x3.y), eh[13], a5);
    a6 = __hfma2(u2h(x3.z), eh[14], a6);
    a7 = __hfma2(u2h(x3.w), eh[15], a7);
#pragma unroll
    for (int k = 4; k < 16; k += 4) {
        uint4 y0 = vv[k];
        uint4 y1 = vv[k + 1];
        uint4 y2 = vv[k + 2];
        uint4 y3 = vv[k + 3];
        a0 = __hfma2(u2h(y0.x), eh[4 * k + 0],  a0);
        a1 = __hfma2(u2h(y0.y), eh[4 * k + 1],  a1);
        a2 = __hfma2(u2h(y0.z), eh[4 * k + 2],  a2);
        a3 = __hfma2(u2h(y0.w), eh[4 * k + 3],  a3);
        a4 = __hfma2(u2h(y1.x), eh[4 * k + 4],  a4);
        a5 = __hfma2(u2h(y1.y), eh[4 * k + 5],  a5);
        a6 = __hfma2(u2h(y1.z), eh[4 * k + 6],  a6);
        a7 = __hfma2(u2h(y1.w), eh[4 * k + 7],  a7);
        a0 = __hfma2(u2h(y2.x), eh[4 * k + 8],  a0);
        a1 = __hfma2(u2h(y2.y), eh[4 * k + 9],  a1);
        a2 = __hfma2(u2h(y2.z), eh[4 * k + 10], a2);
        a3 = __hfma2(u2h(y2.w), eh[4 * k + 11], a3);
        a4 = __hfma2(u2h(y3.x), eh[4 * k + 12], a4);
        a5 = __hfma2(u2h(y3.y), eh[4 * k + 13], a5);
        a6 = __hfma2(u2h(y3.z), eh[4 * k + 14], a6);
        a7 = __hfma2(u2h(y3.w), eh[4 * k + 15], a7);
    }
    a0 = __hadd2(a0, a4); a1 = __hadd2(a1, a5);
    a2 = __hadd2(a2, a6); a3 = __hadd2(a3, a7);
    a0 = __hadd2(a0, a2); a1 = __hadd2(a1, a3);
    a0 = __hadd2(a0, a1);
    return __low2float(a0) + __high2float(a0);
}

__global__ void __launch_bounds__(256, 1) crf_kernel(
    const float* __restrict__ feats,       // [B, S, T]
    const float* __restrict__ trans,       // [T, T]
    const void*  __restrict__ tags_raw,    // [B, S] int64 OR int32 (auto-detect)
    float* __restrict__ out)
{
    __shared__ __align__(16) __half wsh[2][2][T_];   // [half][buf][j]
    __shared__ float red[2][4];

    const int tid  = threadIdx.x;
    const int h    = tid >> 7;
    const int j    = tid & 127;
    const int lane = tid & 31;
    const int widh = (tid >> 5) & 3;
    const int bar  = h + 1;
    const int hx   = 2 * blockIdx.x + h;
    const int START = T_ - 2, STOP = T_ - 1;

    // ---- detect tags dtype (int64 from jax-x64, or silently-demoted int32) ----
    int is64;
    {
        const int* t32d = (const int*)tags_raw;
        int bad = 0;
#pragma unroll
        for (int k = 0; k < 16; ++k) bad |= t32d[2 * k + 1];
        is64 = (bad == 0);
    }
    const long long* t64 = (const long long*)tags_raw;
    const int*       t32 = (const int*)tags_raw;

    for (int slot = 0; slot < 2; ++slot) {
        const unsigned key = g_task[2 * hx + slot];
        if (key == 0u) break;
        const int len = (key >> 14) & 0x1FF;
        const int b   = (key >> 1) & 0xFF;
        const int dir = key & 1;
        const int m   = (len - 1) >> 1;
        const float* fb = feats + (size_t)b * (S_ * T_);

        if (dir == 0) {
            // ============ FORWARD: alpha_0 -> alpha_m (m rounds) ============
            __half2 eh[T_ / 2];
            {
                const float* tc = trans + j;
#pragma unroll
                for (int q = 0; q < T_ / 2; ++q) {
                    float a  = __expf(tc[(2 * q) * T_]);
                    float cc = __expf(tc[(2 * q + 1) * T_]);
                    eh[q] = __floats2half2_rn(a, cc);
                }
            }
            float p0 = fb[j] + trans[START * T_ + j];
            if (j == 0) red[h][0] = p0;
            BARH(bar);
            const float m0 = red[h][0];
            float N = m0 + LOG128;
            float wregf = __expf(p0 - m0) * 0.0078125f;
            wsh[h][0][j] = __float2half_rn(wregf);
            int buf = 0;

            const float* fp = fb + T_ + j;
            float fnext = *fp;                    // feat[1]
            for (int t = 1; t <= m; ++t) {
                BARH(bar);                        // publishes wsh[h][buf]
                const float f = fnext;
                fp += T_;                         // t+1 <= m+1 <= len-1: safe
                fnext = *fp;
                const float ef = __expf(f);
                float scale;
                float s = hmatvec(wsh[h][buf], eh, N, scale);
                wregf = s * (ef * scale);
                buf ^= 1;
                wsh[h][buf][j] = __float2half_rn(wregf);
            }
            g_alpha[b][j] = wregf;
            if (j == 0) g_Nf[b] = N;

            // ---- gold path score for this chain ----
            const size_t tbase = (size_t)b * S_;
            float g = 0.f;
            for (int tt = j; tt < len; tt += 128) {
                int tag  = is64 ? (int)t64[tbase + tt] : t32[tbase + tt];
                int prev = (tt == 0) ? START
                                     : (is64 ? (int)t64[tbase + tt - 1]
                                             : t32[tbase + tt - 1]);
                g += fb[tt * T_ + tag] + trans[prev * T_ + tag];
            }
            g = warpSum(g);
            if (lane == 0) red[h][widh] = g;
            BARH(bar);
            if (j == 0) {
                int end_id = is64 ? (int)t64[tbase + len - 1]
                                  : t32[tbase + len - 1];
                g_gold[b] = (red[h][0] + red[h][1]) + (red[h][2] + red[h][3])
                          + trans[end_id * T_ + STOP];
            }
        } else {
            // ========= BACKWARD: beta_{len-1} -> beta_m (len-1-m rounds) ====
            const int R = (len - 1) - m;
            __half2 eh[T_ / 2];
            {
                const float2* tr2 = reinterpret_cast<const float2*>(trans + j * T_);
#pragma unroll
                for (int q = 0; q < T_ / 2; ++q) {
                    float2 v = tr2[q];
                    eh[q] = __floats2half2_rn(__expf(v.x), __expf(v.y));
                }
            }
            // u_{len-1}[i] = exp(feat[len-1,i] + trans[i,STOP])
            float p0 = fb[(len - 1) * T_ + j] + trans[j * T_ + STOP];
            if (j == 0) red[h][0] = p0;
            BARH(bar);
            const float m0 = red[h][0];
            float N = m0 + LOG128;
            float wregf = __expf(p0 - m0) * 0.0078125f;
            wsh[h][0][j] = __float2half_rn(wregf);
            int buf = 0;

            const float* fp = fb + (len - 2) * T_ + j;
            float fnext = *fp;                    // feat[len-2]
            for (int r = 0; r < R; ++r) {
                BARH(bar);                        // publishes wsh[h][buf]
                const float f = fnext;
                fp -= T_;                         // down to m-1 >= 62: safe
                fnext = *fp;
                const float ef = __expf(f);
                float scale;
                float s = hmatvec(wsh[h][buf], eh, N, scale);
                float val = s * scale;
                wregf = (r < R - 1) ? val * ef : val;   // beta_m has no ef_m
                buf ^= 1;
                wsh[h][buf][j] = __float2half_rn(wregf);
            }
            g_beta[b][j] = wregf;
            if (j == 0) g_Nb[b] = N;
        }
    }

    __threadfence();                          // publish this CTA's results
    __syncthreads();

    // ---- fused deterministic combine + reduce (last CTA via ticket) ----
    __shared__ unsigned s_rank;
    if (tid == 0) s_rank = atomicAdd(&g_ticket, 1u);
    __syncthreads();
    if (s_rank == NCTA - 1) {
        __threadfence();                      // acquire: see all results
        const int w = tid >> 5;               // warp 0..7, 32 chains each
        float part = 0.f;
        for (int c = 0; c < 32; ++c) {
            int bb = w * 32 + c;
            float pr = 0.f;
#pragma unroll
            for (int q = 0; q < 4; ++q) {
                int i = lane + 32 * q;
                pr += g_alpha[bb][i] * g_beta[bb][i];
            }
            pr = warpSum(pr);                 // full sum in all lanes
            if (lane == 0)
                part += __logf(pr) + g_Nf[bb] + g_Nb[bb] - g_gold[bb];
        }
        __shared__ float sb[8];
        if (lane == 0) sb[w] = part;
        __syncthreads();
        if (tid == 0) {
            float s = 0.f;
#pragma unroll
            for (int i = 0; i < 8; ++i) s += sb[i];
            out[0] = s;
            __threadfence();
            atomicExch(&g_ticket, 0u);        // reset for next replay
        }
    }
}

extern "C" void kernel_launch(void* const* d_in, const int* in_sizes, int n_in,
                              void* d_out, int out_size) {
    const float* feats = (const float*)d_in[0];
    const float* trans = (const float*)d_in[1];
    const void*  tags  = d_in[2];
    const int*   mask  = (const int*)d_in[3];

    prep_kernel<<<1, 2 * B_>>>(mask);
    crf_kernel<<<NCTA, 256>>>(feats, trans, tags, (float*)d_out);
}

// round 16
// speedup vs baseline: 1.1561x; 1.1561x over previous
#include <cuda_runtime.h>
#include <cuda_fp16.h>

// CRF NLL, B=256, S=256, T=128 (126 tags + START/STOP)
// Split-chain fwd/bwd (Z_b = sum_i alpha_m[i]*beta_m[i]) -> 512 tasks of
// depth 63..128 rounds. grid=148, 512 threads = FOUR independent 128-thread
// quarters (own named barrier each, 4 warps/SMSP from 4 independent tasks).
// Task rank r (sorted desc by rounds) -> CTA r%148, quarter r/148.
// Inner loop = validated fp16 HFMA2 matvec, E in registers (fwd: trans
// columns; bwd: rows via transposed copy g_ET, coalesced), per-step
// normalization M=max(w0,w1,w64,w65), fp32 N bookkeeping.
// Last CTA (ticket): log(dot(alpha,beta)) + Nf + Nb - gold, deterministic.

#define B_    256
#define S_    256
#define T_    128
#define NCTA  148
#define NTASK (2 * B_)     // 512
#define NSLOT (4 * NCTA)   // 592
#define LOG128 4.852030263919617f

__device__ float g_alpha[B_][T_];
__device__ float g_beta[B_][T_];
__device__ float g_Nf[B_];
__device__ float g_Nb[B_];
__device__ float g_gold[B_];
__device__ float g_ET[T_ * T_];        // g_ET[j*T+i] = trans[i*T+j]
__device__ unsigned g_task[NSLOT];     // 0 = empty
__device__ unsigned g_ticket;          // zero-init; reset by last CTA

#define BARH(id) \
    asm volatile("bar.sync %0, 128;" :: "r"(id) : "memory")

__device__ __forceinline__ float rcpa(float x) {
    float r; asm("rcp.approx.f32 %0, %1;" : "=f"(r) : "f"(x)); return r;
}
__device__ __forceinline__ __half2 u2h(unsigned u) {
    __half2 h;
    *reinterpret_cast<unsigned*>(&h) = u;
    return h;
}
__device__ __forceinline__ float warpSum(float x) {
#pragma unroll
    for (int o = 16; o; o >>= 1) x += __shfl_xor_sync(0xffffffffu, x, o);
    return x;
}

// ---- prep: lengths -> 512 task keys, bitonic sort desc, scatter to slots,
// ---- and transpose trans into g_ET (for coalesced backward E loads).
// key = (rounds<<23) | (len<<14) | (b<<1) | dir
__global__ void prep_kernel(const int* __restrict__ mask,
                            const float* __restrict__ trans) {
    __shared__ unsigned key[NTASK];
    const int t = threadIdx.x;              // 512 threads
    if (t < B_) {
        const int* mb = mask + t * S_;
        int lo = S_ / 2, hi = S_;           // len in [S/2, S], prefix mask
        while (lo < hi) {
            int mid = (lo + hi) >> 1;
            if (mb[mid]) lo = mid + 1; else hi = mid;
        }
        unsigned len = (unsigned)lo;
        unsigned rf = (len - 1) >> 1;
        unsigned rb = (len - 1) - rf;
        key[2 * t]     = (rf << 23) | (len << 14) | ((unsigned)t << 1);
        key[2 * t + 1] = (rb << 23) | (len << 14) | ((unsigned)t << 1) | 1u;
    }
    __syncthreads();
    for (int k = 2; k <= NTASK; k <<= 1) {
        for (int jj = k >> 1; jj; jj >>= 1) {
            int ixj = t ^ jj;
            if (ixj > t) {
                unsigned a = key[t], c = key[ixj];
                bool up = (t & k) == 0;     // descending
                if (up ? (a < c) : (a > c)) { key[t] = c; key[ixj] = a; }
            }
            __syncthreads();
        }
    }
    g_task[t] = 0u;
    if (t < NSLOT - NTASK) g_task[NTASK + t] = 0u;
    __syncthreads();
    g_task[(t % NCTA) * 4 + (t / NCTA)] = key[t];
    for (int idx = t; idx < T_ * T_; idx += NTASK) {
        int i = idx >> 7, j = idx & 127;
        g_ET[j * T_ + i] = trans[idx];
    }
}

// fp16 matvec over shared vector wsrc with per-step normalization.
__device__ __forceinline__ float hmatvec(const __half* __restrict__ wsrc,
                                         const __half2* __restrict__ eh,
                                         float& N, float& scale)
{
    const uint4* vv = reinterpret_cast<const uint4*>(wsrc);
    unsigned ua = *reinterpret_cast<const unsigned*>(wsrc);
    unsigned ub = *reinterpret_cast<const unsigned*>(wsrc + 64);
    __half2 mm = __hmax2(u2h(ua), u2h(ub));
    float M = fmaxf(__low2float(mm), __high2float(mm));
    scale = rcpa(M) * 0.0078125f;           // 1/(128*M)
    N += __logf(M) + LOG128;

    __half2 a0, a1, a2, a3, a4, a5, a6, a7;
    {
        uint4 y0 = vv[0];
        uint4 y1 = vv[1];
        a0 = __hmul2(u2h(y0.x), eh[0]);
        a1 = __hmul2(u2h(y0.y), eh[1]);
        a2 = __hmul2(u2h(y0.z), eh[2]);
        a3 = __hmul2(u2h(y0.w), eh[3]);
        a4 = __hmul2(u2h(y1.x), eh[4]);
        a5 = __hmul2(u2h(y1.y), eh[5]);
        a6 = __hmul2(u2h(y1.z), eh[6]);
        a7 = __hmul2(u2h(y1.w), eh[7]);
    }
#pragma unroll
    for (int k = 2; k < 16; k += 2) {
        uint4 y0 = vv[k];
        uint4 y1 = vv[k + 1];
        a0 = __hfma2(u2h(y0.x), eh[4 * k + 0], a0);
        a1 = __hfma2(u2h(y0.y), eh[4 * k + 1], a1);
        a2 = __hfma2(u2h(y0.z), eh[4 * k + 2], a2);
        a3 = __hfma2(u2h(y0.w), eh[4 * k + 3], a3);
        a4 = __hfma2(u2h(y1.x), eh[4 * k + 4], a4);
        a5 = __hfma2(u2h(y1.y), eh[4 * k + 5], a5);
        a6 = __hfma2(u2h(y1.z), eh[4 * k + 6], a6);
        a7 = __hfma2(u2h(y1.w), eh[4 * k + 7], a7);
    }
    a0 = __hadd2(a0, a4); a1 = __hadd2(a1, a5);
    a2 = __hadd2(a2, a6); a3 = __hadd2(a3, a7);
    a0 = __hadd2(a0, a2); a1 = __hadd2(a1, a3);
    a0 = __hadd2(a0, a1);
    return __low2float(a0) + __high2float(a0);
}

__global__ void __launch_bounds__(512, 1) crf_kernel(
    const float* __restrict__ feats,       // [B, S, T]
    const float* __restrict__ trans,       // [T, T]
    const void*  __restrict__ tags_raw,    // [B, S] int64 OR int32 (auto-detect)
    float* __restrict__ out)
{
    __shared__ __align__(16) __half wsh[4][2][T_];   // [quarter][buf][j]
    __shared__ float red[4][4];

    const int tid  = threadIdx.x;
    const int qq   = tid >> 7;              // quarter 0..3
    const int j    = tid & 127;
    const int lane = tid & 31;
    const int widh = (tid >> 5) & 3;
    const int bar  = qq + 1;                // named barrier 1..4
    const int START = T_ - 2, STOP = T_ - 1;

    // ---- detect tags dtype (int64 from jax-x64, or silently-demoted int32) ----
    int is64;
    {
        const int* t32d = (const int*)tags_raw;
        int bad = 0;
#pragma unroll
        for (int k = 0; k < 16; ++k) bad |= t32d[2 * k + 1];
        is64 = (bad == 0);
    }
    const long long* t64 = (const long long*)tags_raw;
    const int*       t32 = (const int*)tags_raw;

    const unsigned key = g_task[4 * blockIdx.x + qq];
    if (key != 0u) {
        const int len = (key >> 14) & 0x1FF;
        const int b   = (key >> 1) & 0xFF;
        const int dir = key & 1;             // 0 = fwd, 1 = bwd
        const int m   = (len - 1) >> 1;
        const int rounds = dir ? (len - 1 - m) : m;
        const float* fb = feats + (size_t)b * (S_ * T_);

        // ---- E in registers: fwd -> column j of trans; bwd -> row j via g_ET
        __half2 eh[T_ / 2];
        {
            const float* esrc = dir ? (g_ET + j) : (trans + j);
#pragma unroll
            for (int q = 0; q < T_ / 2; ++q) {
                float a  = __expf(esrc[(2 * q) * T_]);
                float cc = __expf(esrc[(2 * q + 1) * T_]);
                eh[q] = __floats2half2_rn(a, cc);
            }
        }

        // ---- init vector ----
        float p0 = dir ? (fb[(len - 1) * T_ + j] + trans[j * T_ + STOP])
                       : (fb[j] + trans[START * T_ + j]);
        if (j == 0) red[qq][0] = p0;
        BARH(bar);
        const float m0 = red[qq][0];
        float N = m0 + LOG128;
        float wregf = __expf(p0 - m0) * 0.0078125f;
        wsh[qq][0][j] = __float2half_rn(wregf);
        int buf = 0;

        const int fstep = dir ? -T_ : T_;
        const float* fp = dir ? (fb + (len - 2) * T_ + j) : (fb + T_ + j);
        float fnext = *fp;

        for (int r = 0; r < rounds; ++r) {
            BARH(bar);                       // publishes wsh[qq][buf]
            const float f = fnext;           // loaded one round ago
            fp += fstep;
            fnext = *fp;                     // LDG for next round
            const float ef = __expf(f);
            float scale;
            float s = hmatvec(wsh[qq][buf], eh, N, scale);
            float val = s * scale;
            // bwd last round outputs beta_m (no feat factor)
            wregf = (dir && r == rounds - 1) ? val : val * ef;
            buf ^= 1;
            wsh[qq][buf][j] = __float2half_rn(wregf);
        }

        if (dir == 0) {
            g_alpha[b][j] = wregf;
            if (j == 0) g_Nf[b] = N;

            // ---- gold path score for this chain (fwd task owns it) ----
            const size_t tbase = (size_t)b * S_;
            float g = 0.f;
            for (int tt = j; tt < len; tt += 128) {
                int tag  = is64 ? (int)t64[tbase + tt] : t32[tbase + tt];
                int prev = (tt == 0) ? START
                                     : (is64 ? (int)t64[tbase + tt - 1]
                                             : t32[tbase + tt - 1]);
                g += fb[tt * T_ + tag] + trans[prev * T_ + tag];
            }
            g = warpSum(g);
            if (lane == 0) red[qq][widh] = g;
            BARH(bar);
            if (j == 0) {
                int end_id = is64 ? (int)t64[tbase + len - 1]
                                  : t32[tbase + len - 1];
                g_gold[b] = (red[qq][0] + red[qq][1])
                          + (red[qq][2] + red[qq][3])
                          + trans[end_id * T_ + STOP];
            }
        } else {
            g_beta[b][j] = wregf;
            if (j == 0) g_Nb[b] = N;
        }
    }

    __threadfence();                          // publish results
    __syncthreads();

    // ---- fused deterministic combine + reduce (last CTA via ticket) ----
    __shared__ unsigned s_rank;
    if (tid == 0) s_rank = atomicAdd(&g_ticket, 1u);
    __syncthreads();
    if (s_rank == NCTA - 1) {
        __threadfence();                      // acquire: see all results
        const int w = tid >> 5;               // warp 0..15, 16 chains each
        float part = 0.f;
        for (int c = 0; c < 16; ++c) {
            int bb = w * 16 + c;
            float pr = 0.f;
#pragma unroll
            for (int q = 0; q < 4; ++q) {
                int i = lane + 32 * q;
                pr += g_alpha[bb][i] * g_beta[bb][i];
            }
            pr = warpSum(pr);                 // full sum in all lanes
            if (lane == 0)
                part += __logf(pr) + g_Nf[bb] + g_Nb[bb] - g_gold[bb];
        }
        __shared__ float sb[16];
        if (lane == 0) sb[w] = part;
        __syncthreads();
        if (tid == 0) {
            float s = 0.f;
#pragma unroll
            for (int i = 0; i < 16; ++i) s += sb[i];
            out[0] = s;
            __threadfence();
            atomicExch(&g_ticket, 0u);        // reset for next replay
        }
    }
}

extern "C" void kernel_launch(void* const* d_in, const int* in_sizes, int n_in,
                              void* d_out, int out_size) {
    const float* feats = (const float*)d_in[0];
    const float* trans = (const float*)d_in[1];
    const void*  tags  = d_in[2];
    const int*   mask  = (const int*)d_in[3];

    prep_kernel<<<1, NTASK>>>(mask, trans);
    crf_kernel<<<NCTA, 512>>>(feats, trans, tags, (float*)d_out);
}

// round 17
// speedup vs baseline: 1.2568x; 1.0871x over previous
#include <cuda_runtime.h>
#include <cuda_fp16.h>

// CRF NLL, B=256, S=256, T=128 (126 tags + START/STOP)
// Split-chain fwd/bwd (Z_b = sum_i alpha_m[i]*beta_m[i]) -> 512 tasks of
// depth 63..128 rounds. grid=148, 512 threads = FOUR independent 128-thread
// quarters (own named barrier each -> 4 warps/SMSP from independent tasks).
// Task rank r (sorted desc by rounds) -> CTA r%148, quarter r/148.
// E precomputed in fp16 in BOTH layouts by a parallel prep kernel:
//   g_Ef[j][i] = exp(trans[i][j])  (fwd, thread j's column, contiguous)
//   g_Eb[j][i] = exp(trans[j][i])  (bwd, thread j's row,    contiguous)
// Inner loop: fp16 HFMA2 matvec, per-step normalization M=max(w0,w1,w64,w65),
// fp32 N bookkeeping. Last CTA (ticket): log(dot)+Nf+Nb-gold, deterministic.

#define B_    256
#define S_    256
#define T_    128
#define NCTA  148
#define NTASK (2 * B_)     // 512
#define NSLOT (4 * NCTA)   // 592
#define LOG128 4.852030263919617f

__device__ float g_alpha[B_][T_];
__device__ float g_beta[B_][T_];
__device__ float g_Nf[B_];
__device__ float g_Nb[B_];
__device__ float g_gold[B_];
__device__ __half g_Ef[T_ * T_];       // [j][i] = exp(trans[i][j])
__device__ __half g_Eb[T_ * T_];       // [j][i] = exp(trans[j][i])
__device__ unsigned g_task[NSLOT];     // 0 = empty
__device__ unsigned g_ticket;          // zero-init; reset by last CTA

#define BARH(id) \
    asm volatile("bar.sync %0, 128;" :: "r"(id) : "memory")

__device__ __forceinline__ float rcpa(float x) {
    float r; asm("rcp.approx.f32 %0, %1;" : "=f"(r) : "f"(x)); return r;
}
__device__ __forceinline__ __half2 u2h(unsigned u) {
    __half2 h;
    *reinterpret_cast<unsigned*>(&h) = u;
    return h;
}
__device__ __forceinline__ float warpSum(float x) {
#pragma unroll
    for (int o = 16; o; o >>= 1) x += __shfl_xor_sync(0xffffffffu, x, o);
    return x;
}

// ---- prep A (parallel): E matrices in fp16, both layouts, coalesced ----
__global__ void prep_emat(const float* __restrict__ trans) {
    const int j = blockIdx.x;               // 128 blocks
    const int i = threadIdx.x;              // 128 threads
    g_Ef[j * T_ + i] = __float2half_rn(__expf(trans[i * T_ + j]));
    g_Eb[j * T_ + i] = __float2half_rn(__expf(trans[j * T_ + i]));
}

// ---- prep B (1 block): lengths -> 512 task keys, bitonic sort desc,
// ---- scatter to CTA/quarter slots.  key = (rounds<<23)|(len<<14)|(b<<1)|dir
__global__ void prep_sort(const int* __restrict__ mask) {
    __shared__ unsigned key[NTASK];
    const int t = threadIdx.x;              // 512 threads
    if (t < B_) {
        const int* mb = mask + t * S_;
        int lo = S_ / 2, hi = S_;           // len in [S/2, S], prefix mask
        while (lo < hi) {
            int mid = (lo + hi) >> 1;
            if (mb[mid]) lo = mid + 1; else hi = mid;
        }
        unsigned len = (unsigned)lo;
        unsigned rf = (len - 1) >> 1;
        unsigned rb = (len - 1) - rf;
        key[2 * t]     = (rf << 23) | (len << 14) | ((unsigned)t << 1);
        key[2 * t + 1] = (rb << 23) | (len << 14) | ((unsigned)t << 1) | 1u;
    }
    __syncthreads();
    for (int k = 2; k <= NTASK; k <<= 1) {
        for (int jj = k >> 1; jj; jj >>= 1) {
            int ixj = t ^ jj;
            if (ixj > t) {
                unsigned a = key[t], c = key[ixj];
                bool up = (t & k) == 0;     // descending
                if (up ? (a < c) : (a > c)) { key[t] = c; key[ixj] = a; }
            }
            __syncthreads();
        }
    }
    g_task[t] = 0u;
    if (t < NSLOT - NTASK) g_task[NTASK + t] = 0u;
    __syncthreads();
    g_task[(t % NCTA) * 4 + (t / NCTA)] = key[t];
}

// fp16 matvec over shared vector wsrc with per-step normalization.
__device__ __forceinline__ float hmatvec(const __half* __restrict__ wsrc,
                                         const __half2* __restrict__ eh,
                                         float& N, float& scale)
{
    const uint4* vv = reinterpret_cast<const uint4*>(wsrc);
    unsigned ua = *reinterpret_cast<const unsigned*>(wsrc);
    unsigned ub = *reinterpret_cast<const unsigned*>(wsrc + 64);
    __half2 mm = __hmax2(u2h(ua), u2h(ub));
    float M = fmaxf(__low2float(mm), __high2float(mm));
    scale = rcpa(M) * 0.0078125f;           // 1/(128*M)
    N += __logf(M) + LOG128;

    __half2 a0, a1, a2, a3, a4, a5, a6, a7;
    {
        uint4 y0 = vv[0];
        uint4 y1 = vv[1];
        a0 = __hmul2(u2h(y0.x), eh[0]);
        a1 = __hmul2(u2h(y0.y), eh[1]);
        a2 = __hmul2(u2h(y0.z), eh[2]);
        a3 = __hmul2(u2h(y0.w), eh[3]);
        a4 = __hmul2(u2h(y1.x), eh[4]);
        a5 = __hmul2(u2h(y1.y), eh[5]);
        a6 = __hmul2(u2h(y1.z), eh[6]);
        a7 = __hmul2(u2h(y1.w), eh[7]);
    }
#pragma unroll
    for (int k = 2; k < 16; k += 2) {
        uint4 y0 = vv[k];
        uint4 y1 = vv[k + 1];
        a0 = __hfma2(u2h(y0.x), eh[4 * k + 0], a0);
        a1 = __hfma2(u2h(y0.y), eh[4 * k + 1], a1);
        a2 = __hfma2(u2h(y0.z), eh[4 * k + 2], a2);
        a3 = __hfma2(u2h(y0.w), eh[4 * k + 3], a3);
        a4 = __hfma2(u2h(y1.x), eh[4 * k + 4], a4);
        a5 = __hfma2(u2h(y1.y), eh[4 * k + 5], a5);
        a6 = __hfma2(u2h(y1.z), eh[4 * k + 6], a6);
        a7 = __hfma2(u2h(y1.w), eh[4 * k + 7], a7);
    }
    a0 = __hadd2(a0, a4); a1 = __hadd2(a1, a5);
    a2 = __hadd2(a2, a6); a3 = __hadd2(a3, a7);
    a0 = __hadd2(a0, a2); a1 = __hadd2(a1, a3);
    a0 = __hadd2(a0, a1);
    return __low2float(a0) + __high2float(a0);
}

__global__ void __launch_bounds__(512, 1) crf_kernel(
    const float* __restrict__ feats,       // [B, S, T]
    const float* __restrict__ trans,       // [T, T]
    const void*  __restrict__ tags_raw,    // [B, S] int64 OR int32 (auto-detect)
    float* __restrict__ out)
{
    __shared__ __align__(16) __half wsh[4][2][T_];   // [quarter][buf][j]
    __shared__ float red[4][4];

    const int tid  = threadIdx.x;
    const int qq   = tid >> 7;              // quarter 0..3
    const int j    = tid & 127;
    const int lane = tid & 31;
    const int widh = (tid >> 5) & 3;
    const int bar  = qq + 1;                // named barrier 1..4
    const int START = T_ - 2, STOP = T_ - 1;

    // ---- detect tags dtype (int64 from jax-x64, or silently-demoted int32) ----
    int is64;
    {
        const int* t32d = (const int*)tags_raw;
        int bad = 0;
#pragma unroll
        for (int k = 0; k < 16; ++k) bad |= t32d[2 * k + 1];
        is64 = (bad == 0);
    }
    const long long* t64 = (const long long*)tags_raw;
    const int*       t32 = (const int*)tags_raw;

    const unsigned key = g_task[4 * blockIdx.x + qq];
    if (key != 0u) {
        const int len = (key >> 14) & 0x1FF;
        const int b   = (key >> 1) & 0xFF;
        const int dir = key & 1;             // 0 = fwd, 1 = bwd
        const int m   = (len - 1) >> 1;
        const int rounds = dir ? (len - 1 - m) : m;
        const float* fb = feats + (size_t)b * (S_ * T_);

        // ---- E in registers: 16 contiguous uint4 loads from fp16 table ----
        __half2 eh[T_ / 2];
        {
            const uint4* ev = reinterpret_cast<const uint4*>(
                (dir ? g_Eb : g_Ef) + j * T_);
#pragma unroll
            for (int q = 0; q < 16; ++q) {
                uint4 v = ev[q];
                eh[4 * q + 0] = u2h(v.x);
                eh[4 * q + 1] = u2h(v.y);
                eh[4 * q + 2] = u2h(v.z);
                eh[4 * q + 3] = u2h(v.w);
            }
        }

        // ---- init vector ----
        float p0 = dir ? (fb[(len - 1) * T_ + j] + trans[j * T_ + STOP])
                       : (fb[j] + trans[START * T_ + j]);
        if (j == 0) red[qq][0] = p0;
        BARH(bar);
        const float m0 = red[qq][0];
        float N = m0 + LOG128;
        float wregf = __expf(p0 - m0) * 0.0078125f;
        wsh[qq][0][j] = __float2half_rn(wregf);
        int buf = 0;

        const int fstep = dir ? -T_ : T_;
        const float* fp = dir ? (fb + (len - 2) * T_ + j) : (fb + T_ + j);
        float fnext = *fp;

        for (int r = 0; r < rounds; ++r) {
            BARH(bar);                       // publishes wsh[qq][buf]
            const float f = fnext;           // loaded one round ago
            fp += fstep;
            fnext = *fp;                     // LDG for next round
            const float ef = __expf(f);
            float scale;
            float s = hmatvec(wsh[qq][buf], eh, N, scale);
            float val = s * scale;
            // bwd last round outputs beta_m (no feat factor)
            wregf = (dir && r == rounds - 1) ? val : val * ef;
            buf ^= 1;
            wsh[qq][buf][j] = __float2half_rn(wregf);
        }

        if (dir == 0) {
            g_alpha[b][j] = wregf;
            if (j == 0) g_Nf[b] = N;

            // ---- gold path score for this chain (fwd task owns it) ----
            const size_t tbase = (size_t)b * S_;
            float g = 0.f;
            for (int tt = j; tt < len; tt += 128) {
                int tag  = is64 ? (int)t64[tbase + tt] : t32[tbase + tt];
                int prev = (tt == 0) ? START
                                     : (is64 ? (int)t64[tbase + tt - 1]
                                             : t32[tbase + tt - 1]);
                g += fb[tt * T_ + tag] + trans[prev * T_ + tag];
            }
            g = warpSum(g);
            if (lane == 0) red[qq][widh] = g;
            BARH(bar);
            if (j == 0) {
                int end_id = is64 ? (int)t64[tbase + len - 1]
                                  : t32[tbase + len - 1];
                g_gold[b] = (red[qq][0] + red[qq][1])
                          + (red[qq][2] + red[qq][3])
                          + trans[end_id * T_ + STOP];
            }
        } else {
            g_beta[b][j] = wregf;
            if (j == 0) g_Nb[b] = N;
        }
    }

    __threadfence();                          // publish results
    __syncthreads();

    // ---- fused deterministic combine + reduce (last CTA via ticket) ----
    __shared__ unsigned s_rank;
    if (tid == 0) s_rank = atomicAdd(&g_ticket, 1u);
    __syncthreads();
    if (s_rank == NCTA - 1) {
        __threadfence();                      // acquire: see all results
        const int w = tid >> 5;               // warp 0..15, 16 chains each
        float part = 0.f;
        for (int c = 0; c < 16; ++c) {
            int bb = w * 16 + c;
            float pr = 0.f;
#pragma unroll
            for (int q = 0; q < 4; ++q) {
                int i = lane + 32 * q;
                pr += g_alpha[bb][i] * g_beta[bb][i];
            }
            pr = warpSum(pr);                 // full sum in all lanes
            if (lane == 0)
                part += __logf(pr) + g_Nf[bb] + g_Nb[bb] - g_gold[bb];
        }
        __shared__ float sb[16];
        if (lane == 0) sb[w] = part;
        __syncthreads();
        if (tid == 0) {
            float s = 0.f;
#pragma unroll
            for (int i = 0; i < 16; ++i) s += sb[i];
            out[0] = s;
            __threadfence();
            atomicExch(&g_ticket, 0u);        // reset for next replay
        }
    }
}

extern "C" void kernel_launch(void* const* d_in, const int* in_sizes, int n_in,
                              void* d_out, int out_size) {
    const float* feats = (const float*)d_in[0];
    const float* trans = (const float*)d_in[1];
    const void*  tags  = d_in[2];
    const int*   mask  = (const int*)d_in[3];

    prep_emat<<<T_, T_>>>(trans);
    prep_sort<<<1, NTASK>>>(mask);
    crf_kernel<<<NCTA, 512>>>(feats, trans, tags, (float*)d_out);
}